// round 12
// baseline (speedup 1.0000x reference)
#include <cuda_runtime.h>
#include <stdint.h>

// Block-sparse linear, GB300 (harness PTX = compute_103 -> no tcgen05/TMA).
// cp.async 2-stage / 1-barrier-per-iter pipeline + warp-level mma.sync tf32.
// MTILE=256 x N=16 per CTA (256 threads): halves barrier count + w traffic per output,
// doubles the prefetch latency window vs MTILE=128.
#define KDIM 4096
#define NDIM 4096
#define MROWS 8192
#define NBR 256       // OUT/16 block rows
#define NBC 256       // IN/16 block cols
#define MAXB 96       // cap on nonzero blocks per row (mean 25.6)
#define MTILE 256
#define NTHR 256
#define XSTR 20       // padded floats per smem row (80B; conflict-free A-column reads)
#define WSTR 20

// ---------------- device globals (no dynamic allocation allowed) ----------------
__device__ int g_cnt[NBR];
__device__ unsigned short g_cols[NBR * MAXB];

// ---------------- helpers ----------------
__device__ __forceinline__ uint32_t smem_u32(const void* p) {
    uint32_t a;
    asm("{ .reg .u64 t; cvta.to.shared.u64 t, %1; cvt.u32.u64 %0, t; }" : "=r"(a) : "l"(p));
    return a;
}
__device__ __forceinline__ void cp16(uint32_t dst, const void* src) {
    asm volatile("cp.async.cg.shared.global [%0], [%1], 16;" :: "r"(dst), "l"(src) : "memory");
}
__device__ __forceinline__ uint32_t cvt_tf32(float f) {
    uint32_t r;
    asm("cvt.rna.tf32.f32 %0, %1;" : "=r"(r) : "f"(f));
    return r;
}
__device__ __forceinline__ void mma_tf32(float* c, const uint32_t* a, const uint32_t* b) {
    asm volatile(
        "mma.sync.aligned.m16n8k8.row.col.f32.tf32.tf32.f32 "
        "{%0,%1,%2,%3}, {%4,%5,%6,%7}, {%8,%9}, {%0,%1,%2,%3};"
        : "+f"(c[0]), "+f"(c[1]), "+f"(c[2]), "+f"(c[3])
        : "r"(a[0]), "r"(a[1]), "r"(a[2]), "r"(a[3]), "r"(b[0]), "r"(b[1]));
}

// ---------------- kernel 1: detect mask dtype + build per-row nonzero block lists ----------------
__global__ void build_lists_kernel(const void* __restrict__ mask) {
    __shared__ int s_es;
    if (threadIdx.x == 0) {
        // Mask is 16x16-block-repeated, so aligned 4-byte words are:
        //   f32: 0 / 0x3F800000   i32: 0 / 1   u8: 0 / 0x01010101   (b)f16: 0 / 0x3F803F80 / 0x3C003C00
        const unsigned* w = (const unsigned*)mask;
        int es = 1;
        for (int i = 0; i < 4096; i++) {
            unsigned v = w[i];
            if (v == 0u) continue;
            if (v == 0x3F800000u) { es = 4; break; }
            if (v == 1u)          { es = 4; break; }
            if (v == 0x01010101u) { es = 1; break; }
            if (v == 0x3F803F80u || v == 0x3C003C00u) { es = 2; break; }
            es = 4; break;
        }
        s_es = es;
    }
    __syncthreads();
    const int es = s_es;
    const int r = threadIdx.x;  // 256 threads, one block row each
    int n = 0;
    for (int c = 0; c < NBC; c++) {
        size_t idx = (size_t)(r * 16) * KDIM + (size_t)c * 16;  // block corner probe
        bool nz;
        if (es == 4)      nz = ((const unsigned*)mask)[idx] != 0u;
        else if (es == 2) nz = ((const unsigned short*)mask)[idx] != 0;
        else              nz = ((const unsigned char*)mask)[idx] != 0;
        if (nz && n < MAXB) { g_cols[r * MAXB + n] = (unsigned short)c; n++; }
    }
    g_cnt[r] = n;
}

// ---------------- kernel 2: block-sparse GEMM via mma.sync tf32, M=256 N=16 per CTA ----------------
__global__ void __launch_bounds__(NTHR, 5)
bs_main_kernel(const float* __restrict__ x, const float* __restrict__ w,
               const float* __restrict__ bias, float* __restrict__ out) {
    __shared__ float sX[2][MTILE * XSTR];   // 2 x 20.5KB
    __shared__ float sW[2][16 * WSTR];      // 2 x 1.25KB
    __shared__ unsigned short s_cols[MAXB];

    const int r     = blockIdx.x;           // block row (fast: L2 locality over x M-slab)
    const int mBase = blockIdx.y * MTILE;   // M tile
    const int tid = threadIdx.x;
    const int wid = tid >> 5;
    const int lid = tid & 31;

    const int cnt = g_cnt[r];
    if (tid < cnt) s_cols[tid] = g_cols[r * MAXB + tid];
    __syncthreads();

    const int ocol = r * 16;

    if (cnt == 0) {
        // no nonzero blocks: output = bias (d_out is poisoned, must still write)
        float4 b0 = *(const float4*)(bias + ocol);
        float4 b1 = *(const float4*)(bias + ocol + 4);
        float4 b2 = *(const float4*)(bias + ocol + 8);
        float4 b3 = *(const float4*)(bias + ocol + 12);
        float4* dst = (float4*)(out + (size_t)(mBase + tid) * NDIM + ocol);
        dst[0] = b0; dst[1] = b1; dst[2] = b2; dst[3] = b3;
        return;
    }

    const uint32_t xs[2] = { smem_u32(&sX[0][0]), smem_u32(&sX[1][0]) };
    const uint32_t ws[2] = { smem_u32(&sW[0][0]), smem_u32(&sW[1][0]) };

    // Coalesced x fill: 4 consecutive lanes cover 64B of one row (8 lines/instr).
    const int frow = tid >> 2;   // 0..63: row within 64-row group
    const int fv   = tid & 3;    // 16B chunk within row
    const float* xbase = x + (size_t)(mBase + frow) * KDIM + fv * 4;

    auto fill = [&](int s, int p) {
        if (p < cnt) {
            const int col = (int)s_cols[p] * 16;
            const float* srcx = xbase + col;
            const uint32_t xd = xs[s] + (uint32_t)(frow * XSTR + fv * 4) * 4;
            #pragma unroll
            for (int i = 0; i < 4; i++)   // rows i*64 + frow
                cp16(xd + (uint32_t)(i * 64 * XSTR) * 4, srcx + (size_t)(i * 64) * KDIM);
            if (tid < 64) {
                const int o = tid >> 2, v = tid & 3;
                cp16(ws[s] + (uint32_t)(o * WSTR + v * 4) * 4,
                     w + (size_t)(ocol + o) * KDIM + col + v * 4);
            }
        }
        asm volatile("cp.async.commit_group;" ::: "memory");  // always: 1 group per iter
    };

    float acc[4][4];
    #pragma unroll
    for (int i = 0; i < 4; i++)
        #pragma unroll
        for (int j = 0; j < 4; j++) acc[i][j] = 0.0f;

    const int g = lid >> 2;    // groupID (0..7)
    const int t4 = lid & 3;    // threadID_in_group (0..3)

    fill(0, 0);

    for (int q = 0; q < cnt; q++) {
        const int s = q & 1;
        // this thread's async copies for block q have landed
        asm volatile("cp.async.wait_group 0;" ::: "memory");
        // (a) publish stage s to all warps, (b) all warps done reading stage s^1 (iter q-1)
        __syncthreads();
        fill(s ^ 1, q + 1);   // depth-1 prefetch into freed stage

        const uint32_t* xb = (const uint32_t*)&sX[s][0];   // raw fp32 bits as tf32 (trunc)
        const float*    wb = &sW[s][0];

        #pragma unroll
        for (int ks = 0; ks < 2; ks++) {
            const int k0 = ks * 8 + t4;
            uint32_t a[2][4], b[2][2];
            #pragma unroll
            for (int mf = 0; mf < 2; mf++) {           // warp covers rows wid*32 .. +31
                const uint32_t* base = xb + (wid * 32 + mf * 16 + g) * XSTR;
                a[mf][0] = base[k0];
                a[mf][1] = base[8 * XSTR + k0];
                a[mf][2] = base[k0 + 4];
                a[mf][3] = base[8 * XSTR + k0 + 4];
            }
            #pragma unroll
            for (int nf = 0; nf < 2; nf++) {
                const float* base = wb + (nf * 8 + g) * WSTR;  // w[o][i] == col-major B
                b[nf][0] = cvt_tf32(base[k0]);
                b[nf][1] = cvt_tf32(base[k0 + 4]);
            }
            #pragma unroll
            for (int mf = 0; mf < 2; mf++)
                #pragma unroll
                for (int nf = 0; nf < 2; nf++)
                    mma_tf32(acc[mf * 2 + nf], a[mf], b[nf]);
        }
    }

    // Epilogue: c0,c1 = C[g][2*t4, 2*t4+1]; c2,c3 = C[g+8][...]
    #pragma unroll
    for (int nf = 0; nf < 2; nf++) {
        const int col = ocol + nf * 8 + t4 * 2;
        const float b0 = bias[col];
        const float b1 = bias[col + 1];
        #pragma unroll
        for (int mf = 0; mf < 2; mf++) {
            const float* c = acc[mf * 2 + nf];
            const int row0 = mBase + wid * 32 + mf * 16 + g;
            float2 v0 = make_float2(c[0] + b0, c[1] + b1);
            float2 v1 = make_float2(c[2] + b0, c[3] + b1);
            *(float2*)(out + (size_t)row0 * NDIM + col) = v0;
            *(float2*)(out + (size_t)(row0 + 8) * NDIM + col) = v1;
        }
    }
}

// ---------------- launch ----------------
extern "C" void kernel_launch(void* const* d_in, const int* in_sizes, int n_in,
                              void* d_out, int out_size) {
    const float* x    = (const float*)d_in[0];
    const float* wgt  = (const float*)d_in[1];
    const float* bias = (const float*)d_in[2];
    const void*  mask = d_in[3];
    float* out = (float*)d_out;

    build_lists_kernel<<<1, 256>>>(mask);
    dim3 grid(NBR, MROWS / MTILE);  // blockIdx.x = block row (fast), blockIdx.y = M tile
    bs_main_kernel<<<grid, NTHR>>>(x, wgt, bias, out);
}

// round 13
// speedup vs baseline: 1.6174x; 1.6174x over previous
#include <cuda_runtime.h>
#include <stdint.h>

// Block-sparse linear, GB300 (harness PTX = compute_103 -> no tcgen05/TMA).
// Round 13 design: pre-pass transforms x and w into FRAGMENT-MAJOR tf32 layouts;
// main kernel is barrier-free LDG.128 global->register -> mma.sync tf32.
#define KDIM 4096
#define NDIM 4096
#define MROWS 8192
#define NBR 256       // OUT/16 block rows
#define NBC 256       // IN/16 block cols
#define MAXB 96       // cap on nonzero blocks per row (mean 25.6)
#define MTILE 128

// ---------------- device globals (no dynamic allocation allowed) ----------------
__device__ int g_cnt[NBR];
__device__ unsigned short g_cols[NBR * MAXB];
// xT: [c(256)][g32(256)][w=mf*2+ks(4)][lane(32)] x uint4  (134MB)
//   thread(lane=g*4+t4) quad = tf32( x[g32*32+mf*16+g][c*16+ks*8+t4], x[..+8][same],
//                                    x[..][col+4], x[..+8][col+4] )
__device__ uint4 g_xT[(size_t)NBC * 256 * 4 * 32];
// wT: [r(256)][c(256)][ks(2)][lane(32)] x uint4  (67MB)
//   quad = tf32( w[r*16+g][c*16+ks*8+t4], w[..][+4], w[r*16+8+g][..], w[..][+4] )
__device__ uint4 g_wT[(size_t)NBR * NBC * 2 * 32];

// ---------------- helpers ----------------
__device__ __forceinline__ uint32_t cvt_tf32(float f) {
    uint32_t r;
    asm("cvt.rna.tf32.f32 %0, %1;" : "=r"(r) : "f"(f));
    return r;
}
__device__ __forceinline__ void mma_tf32(float* c, const uint4& a, uint32_t b0, uint32_t b1) {
    asm volatile(
        "mma.sync.aligned.m16n8k8.row.col.f32.tf32.tf32.f32 "
        "{%0,%1,%2,%3}, {%4,%5,%6,%7}, {%8,%9}, {%0,%1,%2,%3};"
        : "+f"(c[0]), "+f"(c[1]), "+f"(c[2]), "+f"(c[3])
        : "r"(a.x), "r"(a.y), "r"(a.z), "r"(a.w), "r"(b0), "r"(b1));
}

// ---------------- kernel 1: detect mask dtype + build per-row nonzero block lists ----------------
__global__ void build_lists_kernel(const void* __restrict__ mask) {
    __shared__ int s_es;
    if (threadIdx.x == 0) {
        // Mask is 16x16-block-repeated; aligned 4-byte words are:
        //   f32: 0 / 0x3F800000   i32: 0 / 1   u8: 0 / 0x01010101   (b)f16: 0 / 0x3F803F80 / 0x3C003C00
        const unsigned* w = (const unsigned*)mask;
        int es = 1;
        for (int i = 0; i < 4096; i++) {
            unsigned v = w[i];
            if (v == 0u) continue;
            if (v == 0x3F800000u) { es = 4; break; }
            if (v == 1u)          { es = 4; break; }
            if (v == 0x01010101u) { es = 1; break; }
            if (v == 0x3F803F80u || v == 0x3C003C00u) { es = 2; break; }
            es = 4; break;
        }
        s_es = es;
    }
    __syncthreads();
    const int es = s_es;
    const int r = threadIdx.x;  // 256 threads, one block row each
    int n = 0;
    for (int c = 0; c < NBC; c++) {
        size_t idx = (size_t)(r * 16) * KDIM + (size_t)c * 16;  // block corner probe
        bool nz;
        if (es == 4)      nz = ((const unsigned*)mask)[idx] != 0u;
        else if (es == 2) nz = ((const unsigned short*)mask)[idx] != 0;
        else              nz = ((const unsigned char*)mask)[idx] != 0;
        if (nz && n < MAXB) { g_cols[r * MAXB + n] = (unsigned short)c; n++; }
    }
    g_cnt[r] = n;
}

// ---------------- kernel 2: x -> fragment-major tf32 ----------------
__global__ void __launch_bounds__(128)
x_transform_kernel(const float* __restrict__ x) {
    const int c   = blockIdx.x;      // k-block
    const int g32 = blockIdx.y;      // 32-row group
    const int w    = threadIdx.x >> 5;   // mf*2+ks
    const int lane = threadIdx.x & 31;
    const int mf = w >> 1, ks = w & 1;
    const int g = lane >> 2, t4 = lane & 3;
    const int r0 = g32 * 32 + mf * 16 + g;
    const int c0 = c * 16 + ks * 8 + t4;
    uint4 v;
    v.x = cvt_tf32(x[(size_t)r0 * KDIM + c0]);
    v.y = cvt_tf32(x[(size_t)(r0 + 8) * KDIM + c0]);
    v.z = cvt_tf32(x[(size_t)r0 * KDIM + c0 + 4]);
    v.w = cvt_tf32(x[(size_t)(r0 + 8) * KDIM + c0 + 4]);
    g_xT[((size_t)(c * 256 + g32) * 4 + w) * 32 + lane] = v;
}

// ---------------- kernel 3: w -> fragment-major tf32 ----------------
__global__ void __launch_bounds__(64)
w_transform_kernel(const float* __restrict__ w) {
    const int c = blockIdx.x;
    const int r = blockIdx.y;
    const int ks   = threadIdx.x >> 5;
    const int lane = threadIdx.x & 31;
    const int g = lane >> 2, t4 = lane & 3;
    const int row = r * 16 + g;
    const int col = c * 16 + ks * 8 + t4;
    uint4 v;
    v.x = cvt_tf32(w[(size_t)row * KDIM + col]);
    v.y = cvt_tf32(w[(size_t)row * KDIM + col + 4]);
    v.z = cvt_tf32(w[(size_t)(row + 8) * KDIM + col]);
    v.w = cvt_tf32(w[(size_t)(row + 8) * KDIM + col + 4]);
    g_wT[((size_t)(r * 256 + c) * 2 + ks) * 32 + lane] = v;
}

// ---------------- kernel 4: main — barrier-free register GEMM ----------------
__global__ void __launch_bounds__(128, 5)
bs_main_kernel(const float* __restrict__ bias, float* __restrict__ out) {
    __shared__ unsigned short s_cols[MAXB];

    const int r     = blockIdx.x;           // block row (fast: L2 locality over x slab)
    const int mBase = blockIdx.y * MTILE;   // M tile
    const int tid = threadIdx.x;
    const int wid = tid >> 5;
    const int lid = tid & 31;
    const int g = lid >> 2, t4 = lid & 3;

    const int cnt = g_cnt[r];
    if (tid < cnt) s_cols[tid] = g_cols[r * MAXB + tid];
    __syncthreads();

    const int ocol = r * 16;

    if (cnt == 0) {
        float4 b0 = *(const float4*)(bias + ocol);
        float4 b1 = *(const float4*)(bias + ocol + 4);
        float4 b2 = *(const float4*)(bias + ocol + 8);
        float4 b3 = *(const float4*)(bias + ocol + 12);
        float4* dst = (float4*)(out + (size_t)(mBase + tid) * NDIM + ocol);
        dst[0] = b0; dst[1] = b1; dst[2] = b2; dst[3] = b3;
        return;
    }

    const size_t g32 = (size_t)blockIdx.y * 4 + wid;   // this warp's 32-row group

    float acc[4][4];
    #pragma unroll
    for (int i = 0; i < 4; i++)
        #pragma unroll
        for (int j = 0; j < 4; j++) acc[i][j] = 0.0f;

    // fragment loaders (pure LDG.128, fully coalesced)
    auto ldfrag = [&](int q, uint4* A, uint4* B) {
        const int c = s_cols[q];
        const uint4* xp = &g_xT[((size_t)c * 256 + g32) * 128 + lid];
        A[0] = xp[0];        // mf0 ks0
        A[1] = xp[32];       // mf0 ks1
        A[2] = xp[64];       // mf1 ks0
        A[3] = xp[96];       // mf1 ks1
        const uint4* wp = &g_wT[((size_t)r * 256 + c) * 64 + lid];
        B[0] = wp[0];        // ks0: (b00,b01,b10,b11)
        B[1] = wp[32];       // ks1
    };

    uint4 A[4], B[2], An[4], Bn[2];
    ldfrag(0, A, B);

    for (int q = 0; q < cnt; q++) {
        const int qn = (q + 1 < cnt) ? q + 1 : q;   // clamped prefetch (branch-free)
        ldfrag(qn, An, Bn);

        #pragma unroll
        for (int ks = 0; ks < 2; ks++) {
            const uint32_t b00 = ks ? B[1].x : B[0].x;
            const uint32_t b01 = ks ? B[1].y : B[0].y;
            const uint32_t b10 = ks ? B[1].z : B[0].z;
            const uint32_t b11 = ks ? B[1].w : B[0].w;
            #pragma unroll
            for (int mf = 0; mf < 2; mf++) {
                const uint4& a = A[mf * 2 + ks];
                mma_tf32(acc[mf * 2 + 0], a, b00, b01);
                mma_tf32(acc[mf * 2 + 1], a, b10, b11);
            }
        }
        #pragma unroll
        for (int i = 0; i < 4; i++) A[i] = An[i];
        B[0] = Bn[0]; B[1] = Bn[1];
    }

    // Epilogue: c0,c1 = C[g][2*t4, 2*t4+1]; c2,c3 = C[g+8][...]
    #pragma unroll
    for (int nf = 0; nf < 2; nf++) {
        const int col = ocol + nf * 8 + t4 * 2;
        const float b0 = bias[col];
        const float b1 = bias[col + 1];
        #pragma unroll
        for (int mf = 0; mf < 2; mf++) {
            const float* c = acc[mf * 2 + nf];
            const int row0 = mBase + wid * 32 + mf * 16 + g;
            float2 v0 = make_float2(c[0] + b0, c[1] + b1);
            float2 v1 = make_float2(c[2] + b0, c[3] + b1);
            *(float2*)(out + (size_t)row0 * NDIM + col) = v0;
            *(float2*)(out + (size_t)(row0 + 8) * NDIM + col) = v1;
        }
    }
}

// ---------------- launch ----------------
extern "C" void kernel_launch(void* const* d_in, const int* in_sizes, int n_in,
                              void* d_out, int out_size) {
    const float* x    = (const float*)d_in[0];
    const float* wgt  = (const float*)d_in[1];
    const float* bias = (const float*)d_in[2];
    const void*  mask = d_in[3];
    float* out = (float*)d_out;

    build_lists_kernel<<<1, 256>>>(mask);
    x_transform_kernel<<<dim3(NBC, MROWS / 32), 128>>>(x);
    w_transform_kernel<<<dim3(NBC, NBR), 64>>>(wgt);
    dim3 grid(NBR, MROWS / MTILE);  // blockIdx.x = block row (fast), blockIdx.y = M tile
    bs_main_kernel<<<grid, 128>>>(bias, out);
}

// round 14
// speedup vs baseline: 1.9831x; 1.2261x over previous
#include <cuda_runtime.h>
#include <stdint.h>

// Block-sparse linear, GB300 (harness PTX = compute_103 -> no tcgen05/TMA).
// R14: same barrier-free fragment-major main kernel as R13 (193.8us);
// pre-pass rebuilt: coalesced smem-staged transforms + parallel list build.
#define KDIM 4096
#define NDIM 4096
#define MROWS 8192
#define NBR 256       // OUT/16 block rows
#define NBC 256       // IN/16 block cols
#define MAXB 96       // cap on nonzero blocks per row (mean 25.6)
#define MTILE 128

// ---------------- device globals (no dynamic allocation allowed) ----------------
__device__ int g_cnt[NBR];
__device__ unsigned short g_cols[NBR * MAXB];
// xT: [c(256)][g32(256)][w=mf*2+ks(4)][lane(32)] x uint4  (134MB)
//   thread(lane=g*4+t4) quad = tf32( x[g32*32+mf*16+g][c*16+ks*8+t4], x[..+8][same],
//                                    x[..][col+4], x[..+8][col+4] )
__device__ uint4 g_xT[(size_t)NBC * 256 * 4 * 32];
// wT: [r(256)][c(256)][ks(2)][lane(32)] x uint4  (67MB)
//   quad = tf32( w[r*16+g][c*16+ks*8+t4], w[..][+4], w[r*16+8+g][..], w[..][+4] )
__device__ uint4 g_wT[(size_t)NBR * NBC * 2 * 32];

// ---------------- helpers ----------------
__device__ __forceinline__ uint32_t cvt_tf32(float f) {
    uint32_t r;
    asm("cvt.rna.tf32.f32 %0, %1;" : "=r"(r) : "f"(f));
    return r;
}
__device__ __forceinline__ void mma_tf32(float* c, const uint4& a, uint32_t b0, uint32_t b1) {
    asm volatile(
        "mma.sync.aligned.m16n8k8.row.col.f32.tf32.tf32.f32 "
        "{%0,%1,%2,%3}, {%4,%5,%6,%7}, {%8,%9}, {%0,%1,%2,%3};"
        : "+f"(c[0]), "+f"(c[1]), "+f"(c[2]), "+f"(c[3])
        : "r"(a.x), "r"(a.y), "r"(a.z), "r"(a.w), "r"(b0), "r"(b1));
}
// mask probe dtype detect (block-repeated pattern; see R4 notes)
__device__ __forceinline__ int detect_es(const void* mask) {
    const unsigned* w = (const unsigned*)mask;
    int es = 1;
    for (int i = 0; i < 4096; i++) {
        unsigned v = w[i];
        if (v == 0u) continue;
        if (v == 0x3F800000u) { es = 4; break; }
        if (v == 1u)          { es = 4; break; }
        if (v == 0x01010101u) { es = 1; break; }
        if (v == 0x3F803F80u || v == 0x3C003C00u) { es = 2; break; }
        es = 4; break;
    }
    return es;
}

// ---------------- kernel 1: parallel per-row nonzero block lists ----------------
__global__ void __launch_bounds__(256)
build_lists_kernel(const void* __restrict__ mask) {
    __shared__ int s_es;
    __shared__ int s_wcnt[8];
    const int r = blockIdx.x;
    const int tid = threadIdx.x;
    if (tid == 0) s_es = detect_es(mask);   // early-exits at first nonzero word
    __syncthreads();
    const int es = s_es;
    const int c = tid;                      // one k-block per thread
    size_t idx = (size_t)(r * 16) * KDIM + (size_t)c * 16;
    bool nz;
    if (es == 4)      nz = ((const unsigned*)mask)[idx] != 0u;
    else if (es == 2) nz = ((const unsigned short*)mask)[idx] != 0;
    else              nz = ((const unsigned char*)mask)[idx] != 0;
    const unsigned ball = __ballot_sync(0xFFFFFFFFu, nz);
    const int wid = tid >> 5, lane = tid & 31;
    if (lane == 0) s_wcnt[wid] = __popc(ball);
    __syncthreads();
    int base = 0;
    #pragma unroll
    for (int i = 0; i < 8; i++) base += (i < wid) ? s_wcnt[i] : 0;
    const int pos = base + __popc(ball & ((1u << lane) - 1u));
    if (nz && pos < MAXB) g_cols[r * MAXB + pos] = (unsigned short)c;
    if (tid == 255) {
        int tot = base + s_wcnt[7];
        g_cnt[r] = tot < MAXB ? tot : MAXB;
    }
}

// ---------------- kernel 2: x -> fragment-major tf32 (smem-staged, coalesced) ----------------
// block: 256 thr, tile = 32 rows (one g32) x 64 cols (4 c-blocks). grid (NBC/4, MROWS/32).
__global__ void __launch_bounds__(256)
x_transform_kernel(const float* __restrict__ x) {
    __shared__ float s[32][68];     // pad 4: LDS banks spread
    const int cbase = blockIdx.x * 4;
    const int g32   = blockIdx.y;
    const int tid = threadIdx.x;

    // load: 32 rows x 16 float4 = 512 float4; 16 lanes per row -> full-line coalesced
    {
        const int row = tid >> 4;          // 0..15 (+16 second pass)
        const int cc  = (tid & 15) * 4;    // float4 within 64-col chunk
        const float* src = x + (size_t)(g32 * 32) * KDIM + cbase * 16;
        #pragma unroll
        for (int h = 0; h < 2; h++) {
            float4 v = *(const float4*)(src + (size_t)(row + h * 16) * KDIM + cc);
            s[row + h * 16][cc]     = v.x;
            s[row + h * 16][cc + 1] = v.y;
            s[row + h * 16][cc + 2] = v.z;
            s[row + h * 16][cc + 3] = v.w;
        }
    }
    __syncthreads();

    // emit: 4 cb x 4 w x 32 lanes = 512 uint4; coalesced 2KB runs per cb
    #pragma unroll
    for (int rep = 0; rep < 2; rep++) {
        const int o    = tid + rep * 256;
        const int cb   = o >> 7;           // 0..3
        const int w    = (o >> 5) & 3;     // mf*2+ks
        const int lane = o & 31;
        const int mf = w >> 1, ks = w & 1;
        const int g = lane >> 2, t4 = lane & 3;
        const int r0 = mf * 16 + g;
        const int cc = cb * 16 + ks * 8 + t4;
        uint4 v;
        v.x = cvt_tf32(s[r0][cc]);
        v.y = cvt_tf32(s[r0 + 8][cc]);
        v.z = cvt_tf32(s[r0][cc + 4]);
        v.w = cvt_tf32(s[r0 + 8][cc + 4]);
        g_xT[((size_t)((cbase + cb) * 256 + g32) * 4 + w) * 32 + lane] = v;
    }
}

// ---------------- kernel 3: w -> fragment-major tf32 (smem-staged, coalesced) ----------------
// block: 256 thr, tile = 16 rows (one r-block) x 64 cols (4 c-blocks). grid (NBC/4, NBR).
__global__ void __launch_bounds__(256)
w_transform_kernel(const float* __restrict__ w) {
    __shared__ float s[16][68];
    const int cbase = blockIdx.x * 4;
    const int r     = blockIdx.y;
    const int tid = threadIdx.x;

    // load: 16 rows x 16 float4 = 256 float4, one per thread; 16 lanes per row
    {
        const int row = tid >> 4;
        const int cc  = (tid & 15) * 4;
        float4 v = *(const float4*)(w + (size_t)(r * 16 + row) * KDIM + cbase * 16 + cc);
        s[row][cc] = v.x; s[row][cc + 1] = v.y; s[row][cc + 2] = v.z; s[row][cc + 3] = v.w;
    }
    __syncthreads();

    // emit: 4 cb x 2 ks x 32 lanes = 256 uint4, one per thread; coalesced 1KB runs per cb
    {
        const int cb   = tid >> 6;         // 0..3
        const int ks   = (tid >> 5) & 1;
        const int lane = tid & 31;
        const int g = lane >> 2, t4 = lane & 3;
        const int cc = cb * 16 + ks * 8 + t4;
        uint4 v;
        v.x = cvt_tf32(s[g][cc]);
        v.y = cvt_tf32(s[g][cc + 4]);
        v.z = cvt_tf32(s[g + 8][cc]);
        v.w = cvt_tf32(s[g + 8][cc + 4]);
        g_wT[((size_t)(r * 256 + (cbase + cb)) * 2 + ks) * 32 + lane] = v;
    }
}

// ---------------- kernel 4: main — barrier-free register GEMM (unchanged from R13) ----------------
__global__ void __launch_bounds__(128, 5)
bs_main_kernel(const float* __restrict__ bias, float* __restrict__ out) {
    __shared__ unsigned short s_cols[MAXB];

    const int r     = blockIdx.x;           // block row (fast: L2 locality over x slab)
    const int mBase = blockIdx.y * MTILE;   // M tile
    const int tid = threadIdx.x;
    const int wid = tid >> 5;
    const int lid = tid & 31;
    const int g = lid >> 2, t4 = lid & 3;

    const int cnt = g_cnt[r];
    if (tid < cnt) s_cols[tid] = g_cols[r * MAXB + tid];
    __syncthreads();

    const int ocol = r * 16;

    if (cnt == 0) {
        float4 b0 = *(const float4*)(bias + ocol);
        float4 b1 = *(const float4*)(bias + ocol + 4);
        float4 b2 = *(const float4*)(bias + ocol + 8);
        float4 b3 = *(const float4*)(bias + ocol + 12);
        float4* dst = (float4*)(out + (size_t)(mBase + tid) * NDIM + ocol);
        dst[0] = b0; dst[1] = b1; dst[2] = b2; dst[3] = b3;
        return;
    }

    const size_t g32 = (size_t)blockIdx.y * 4 + wid;   // this warp's 32-row group

    float acc[4][4];
    #pragma unroll
    for (int i = 0; i < 4; i++)
        #pragma unroll
        for (int j = 0; j < 4; j++) acc[i][j] = 0.0f;

    auto ldfrag = [&](int q, uint4* A, uint4* B) {
        const int c = s_cols[q];
        const uint4* xp = &g_xT[((size_t)c * 256 + g32) * 128 + lid];
        A[0] = xp[0];        // mf0 ks0
        A[1] = xp[32];       // mf0 ks1
        A[2] = xp[64];       // mf1 ks0
        A[3] = xp[96];       // mf1 ks1
        const uint4* wp = &g_wT[((size_t)r * 256 + c) * 64 + lid];
        B[0] = wp[0];        // ks0: (b00,b01,b10,b11)
        B[1] = wp[32];       // ks1
    };

    uint4 A[4], B[2], An[4], Bn[2];
    ldfrag(0, A, B);

    for (int q = 0; q < cnt; q++) {
        const int qn = (q + 1 < cnt) ? q + 1 : q;   // clamped prefetch (branch-free)
        ldfrag(qn, An, Bn);

        #pragma unroll
        for (int ks = 0; ks < 2; ks++) {
            const uint32_t b00 = ks ? B[1].x : B[0].x;
            const uint32_t b01 = ks ? B[1].y : B[0].y;
            const uint32_t b10 = ks ? B[1].z : B[0].z;
            const uint32_t b11 = ks ? B[1].w : B[0].w;
            #pragma unroll
            for (int mf = 0; mf < 2; mf++) {
                const uint4& a = A[mf * 2 + ks];
                mma_tf32(acc[mf * 2 + 0], a, b00, b01);
                mma_tf32(acc[mf * 2 + 1], a, b10, b11);
            }
        }
        #pragma unroll
        for (int i = 0; i < 4; i++) A[i] = An[i];
        B[0] = Bn[0]; B[1] = Bn[1];
    }

    // Epilogue: c0,c1 = C[g][2*t4, 2*t4+1]; c2,c3 = C[g+8][...]
    #pragma unroll
    for (int nf = 0; nf < 2; nf++) {
        const int col = ocol + nf * 8 + t4 * 2;
        const float b0 = bias[col];
        const float b1 = bias[col + 1];
        #pragma unroll
        for (int mf = 0; mf < 2; mf++) {
            const float* c = acc[mf * 2 + nf];
            const int row0 = mBase + wid * 32 + mf * 16 + g;
            float2 v0 = make_float2(c[0] + b0, c[1] + b1);
            float2 v1 = make_float2(c[2] + b0, c[3] + b1);
            *(float2*)(out + (size_t)row0 * NDIM + col) = v0;
            *(float2*)(out + (size_t)(row0 + 8) * NDIM + col) = v1;
        }
    }
}

// ---------------- launch ----------------
extern "C" void kernel_launch(void* const* d_in, const int* in_sizes, int n_in,
                              void* d_out, int out_size) {
    const float* x    = (const float*)d_in[0];
    const float* wgt  = (const float*)d_in[1];
    const float* bias = (const float*)d_in[2];
    const void*  mask = d_in[3];
    float* out = (float*)d_out;

    build_lists_kernel<<<NBR, 256>>>(mask);
    x_transform_kernel<<<dim3(NBC / 4, MROWS / 32), 256>>>(x);
    w_transform_kernel<<<dim3(NBC / 4, NBR), 256>>>(wgt);
    dim3 grid(NBR, MROWS / MTILE);  // blockIdx.x = block row (fast), blockIdx.y = M tile
    bs_main_kernel<<<grid, 128>>>(bias, out);
}

// round 15
// speedup vs baseline: 2.1198x; 1.0689x over previous
#include <cuda_runtime.h>
#include <stdint.h>

// Block-sparse linear, GB300 (harness PTX = compute_103 -> no tcgen05/TMA).
// R15: fragment-major tf32 layout (R13/R14 pre-pass) + main kernel with M=64 per warp
// (B-fragment amortization: 24 -> 20 wavefronts per 32-row unit) and ping-pong unroll.
#define KDIM 4096
#define NDIM 4096
#define MROWS 8192
#define NBR 256       // OUT/16 block rows
#define NBC 256       // IN/16 block cols
#define MAXB 96       // cap on nonzero blocks per row (mean 25.6)
#define MTILE 256

// ---------------- device globals (no dynamic allocation allowed) ----------------
__device__ int g_cnt[NBR];
__device__ unsigned short g_cols[NBR * MAXB];
// xT: [c(256)][g32(256)][w=mf*2+ks(4)][lane(32)] x uint4  (134MB)
__device__ uint4 g_xT[(size_t)NBC * 256 * 4 * 32];
// wT: [r(256)][c(256)][ks(2)][lane(32)] x uint4  (67MB)
__device__ uint4 g_wT[(size_t)NBR * NBC * 2 * 32];

// ---------------- helpers ----------------
__device__ __forceinline__ uint32_t cvt_tf32(float f) {
    uint32_t r;
    asm("cvt.rna.tf32.f32 %0, %1;" : "=r"(r) : "f"(f));
    return r;
}
__device__ __forceinline__ void mma_tf32(float* c, const uint4& a, uint32_t b0, uint32_t b1) {
    asm volatile(
        "mma.sync.aligned.m16n8k8.row.col.f32.tf32.tf32.f32 "
        "{%0,%1,%2,%3}, {%4,%5,%6,%7}, {%8,%9}, {%0,%1,%2,%3};"
        : "+f"(c[0]), "+f"(c[1]), "+f"(c[2]), "+f"(c[3])
        : "r"(a.x), "r"(a.y), "r"(a.z), "r"(a.w), "r"(b0), "r"(b1));
}
__device__ __forceinline__ int detect_es(const void* mask) {
    const unsigned* w = (const unsigned*)mask;
    int es = 1;
    for (int i = 0; i < 4096; i++) {
        unsigned v = w[i];
        if (v == 0u) continue;
        if (v == 0x3F800000u) { es = 4; break; }
        if (v == 1u)          { es = 4; break; }
        if (v == 0x01010101u) { es = 1; break; }
        if (v == 0x3F803F80u || v == 0x3C003C00u) { es = 2; break; }
        es = 4; break;
    }
    return es;
}

// ---------------- kernel 1: parallel per-row nonzero block lists ----------------
__global__ void __launch_bounds__(256)
build_lists_kernel(const void* __restrict__ mask) {
    __shared__ int s_es;
    __shared__ int s_wcnt[8];
    const int r = blockIdx.x;
    const int tid = threadIdx.x;
    if (tid == 0) s_es = detect_es(mask);
    __syncthreads();
    const int es = s_es;
    const int c = tid;
    size_t idx = (size_t)(r * 16) * KDIM + (size_t)c * 16;
    bool nz;
    if (es == 4)      nz = ((const unsigned*)mask)[idx] != 0u;
    else if (es == 2) nz = ((const unsigned short*)mask)[idx] != 0;
    else              nz = ((const unsigned char*)mask)[idx] != 0;
    const unsigned ball = __ballot_sync(0xFFFFFFFFu, nz);
    const int wid = tid >> 5, lane = tid & 31;
    if (lane == 0) s_wcnt[wid] = __popc(ball);
    __syncthreads();
    int base = 0;
    #pragma unroll
    for (int i = 0; i < 8; i++) base += (i < wid) ? s_wcnt[i] : 0;
    const int pos = base + __popc(ball & ((1u << lane) - 1u));
    if (nz && pos < MAXB) g_cols[r * MAXB + pos] = (unsigned short)c;
    if (tid == 255) {
        int tot = base + s_wcnt[7];
        g_cnt[r] = tot < MAXB ? tot : MAXB;
    }
}

// ---------------- kernel 2: x -> fragment-major tf32 (smem-staged, coalesced) ----------------
__global__ void __launch_bounds__(256)
x_transform_kernel(const float* __restrict__ x) {
    __shared__ float s[32][68];
    const int cbase = blockIdx.x * 4;
    const int g32   = blockIdx.y;
    const int tid = threadIdx.x;
    {
        const int row = tid >> 4;
        const int cc  = (tid & 15) * 4;
        const float* src = x + (size_t)(g32 * 32) * KDIM + cbase * 16;
        #pragma unroll
        for (int h = 0; h < 2; h++) {
            float4 v = *(const float4*)(src + (size_t)(row + h * 16) * KDIM + cc);
            s[row + h * 16][cc]     = v.x;
            s[row + h * 16][cc + 1] = v.y;
            s[row + h * 16][cc + 2] = v.z;
            s[row + h * 16][cc + 3] = v.w;
        }
    }
    __syncthreads();
    #pragma unroll
    for (int rep = 0; rep < 2; rep++) {
        const int o    = tid + rep * 256;
        const int cb   = o >> 7;
        const int w    = (o >> 5) & 3;
        const int lane = o & 31;
        const int mf = w >> 1, ks = w & 1;
        const int g = lane >> 2, t4 = lane & 3;
        const int r0 = mf * 16 + g;
        const int cc = cb * 16 + ks * 8 + t4;
        uint4 v;
        v.x = cvt_tf32(s[r0][cc]);
        v.y = cvt_tf32(s[r0 + 8][cc]);
        v.z = cvt_tf32(s[r0][cc + 4]);
        v.w = cvt_tf32(s[r0 + 8][cc + 4]);
        g_xT[((size_t)((cbase + cb) * 256 + g32) * 4 + w) * 32 + lane] = v;
    }
}

// ---------------- kernel 3: w -> fragment-major tf32 (smem-staged, coalesced) ----------------
__global__ void __launch_bounds__(256)
w_transform_kernel(const float* __restrict__ w) {
    __shared__ float s[16][68];
    const int cbase = blockIdx.x * 4;
    const int r     = blockIdx.y;
    const int tid = threadIdx.x;
    {
        const int row = tid >> 4;
        const int cc  = (tid & 15) * 4;
        float4 v = *(const float4*)(w + (size_t)(r * 16 + row) * KDIM + cbase * 16 + cc);
        s[row][cc] = v.x; s[row][cc + 1] = v.y; s[row][cc + 2] = v.z; s[row][cc + 3] = v.w;
    }
    __syncthreads();
    {
        const int cb   = tid >> 6;
        const int ks   = (tid >> 5) & 1;
        const int lane = tid & 31;
        const int g = lane >> 2, t4 = lane & 3;
        const int cc = cb * 16 + ks * 8 + t4;
        uint4 v;
        v.x = cvt_tf32(s[g][cc]);
        v.y = cvt_tf32(s[g][cc + 4]);
        v.z = cvt_tf32(s[g + 8][cc]);
        v.w = cvt_tf32(s[g + 8][cc + 4]);
        g_wT[((size_t)(r * 256 + (cbase + cb)) * 2 + ks) * 32 + lane] = v;
    }
}

// ---------------- kernel 4: main — M=64 per warp, ping-pong, barrier-free ----------------
__global__ void __launch_bounds__(128, 3)
bs_main_kernel(const float* __restrict__ bias, float* __restrict__ out) {
    __shared__ unsigned short s_cols[MAXB];

    const int r     = blockIdx.x;            // block row (fast: L2 locality over x slab)
    const int mBase = blockIdx.y * MTILE;    // 256-row M tile
    const int tid = threadIdx.x;
    const int wid = tid >> 5;
    const int lid = tid & 31;
    const int g = lid >> 2, t4 = lid & 3;

    const int cnt = g_cnt[r];
    if (tid < cnt) s_cols[tid] = g_cols[r * MAXB + tid];
    __syncthreads();

    const int ocol = r * 16;

    if (cnt == 0) {
        float4 b0 = *(const float4*)(bias + ocol);
        float4 b1 = *(const float4*)(bias + ocol + 4);
        float4 b2 = *(const float4*)(bias + ocol + 8);
        float4 b3 = *(const float4*)(bias + ocol + 12);
        #pragma unroll
        for (int h = 0; h < 2; h++) {
            float4* dst = (float4*)(out + (size_t)(mBase + h * 128 + tid) * NDIM + ocol);
            dst[0] = b0; dst[1] = b1; dst[2] = b2; dst[3] = b3;
        }
        return;
    }

    // warp covers rows [mBase + wid*64, +64): two consecutive g32 groups
    const size_t g32a = (size_t)blockIdx.y * 8 + wid * 2;

    float acc[8][4];
    #pragma unroll
    for (int i = 0; i < 8; i++)
        #pragma unroll
        for (int j = 0; j < 4; j++) acc[i][j] = 0.0f;

    // A[j], j = mf*2+ks (mf 0..3): xT for g32a at j<4, g32a+1 at j>=4 (contiguous: +128 uint4)
    auto ldfrag = [&](int q, uint4* A, uint4* B) {
        const int c = s_cols[q];
        const uint4* xp = &g_xT[((size_t)c * 256 + g32a) * 128 + lid];
        #pragma unroll
        for (int j = 0; j < 8; j++) A[j] = xp[j * 32];
        const uint4* wp = &g_wT[((size_t)r * 256 + c) * 64 + lid];
        B[0] = wp[0];
        B[1] = wp[32];
    };

    auto compute = [&](const uint4* A, const uint4* B) {
        #pragma unroll
        for (int ks = 0; ks < 2; ks++) {
            const uint32_t b00 = B[ks].x;
            const uint32_t b01 = B[ks].y;
            const uint32_t b10 = B[ks].z;
            const uint32_t b11 = B[ks].w;
            #pragma unroll
            for (int mf = 0; mf < 4; mf++) {
                const uint4& a = A[mf * 2 + ks];
                mma_tf32(acc[mf * 2 + 0], a, b00, b01);
                mma_tf32(acc[mf * 2 + 1], a, b10, b11);
            }
        }
    };

    uint4 A0[8], B0[2], A1[8], B1[2];
    ldfrag(0, A0, B0);
    int q = 0;
    for (;;) {
        const int q1 = (q + 1 < cnt) ? q + 1 : q;
        ldfrag(q1, A1, B1);          // prefetch overlaps compute below
        compute(A0, B0);
        if (++q >= cnt) break;
        const int q2 = (q + 1 < cnt) ? q + 1 : q;
        ldfrag(q2, A0, B0);
        compute(A1, B1);
        if (++q >= cnt) break;
    }

    // Epilogue: c0,c1 = C[g][2*t4, 2*t4+1]; c2,c3 = C[g+8][...]
    #pragma unroll
    for (int nf = 0; nf < 2; nf++) {
        const int col = ocol + nf * 8 + t4 * 2;
        const float b0 = bias[col];
        const float b1 = bias[col + 1];
        #pragma unroll
        for (int mf = 0; mf < 4; mf++) {
            const float* c = acc[mf * 2 + nf];
            const int row0 = mBase + wid * 64 + mf * 16 + g;
            float2 v0 = make_float2(c[0] + b0, c[1] + b1);
            float2 v1 = make_float2(c[2] + b0, c[3] + b1);
            *(float2*)(out + (size_t)row0 * NDIM + col) = v0;
            *(float2*)(out + (size_t)(row0 + 8) * NDIM + col) = v1;
        }
    }
}

// ---------------- launch ----------------
extern "C" void kernel_launch(void* const* d_in, const int* in_sizes, int n_in,
                              void* d_out, int out_size) {
    const float* x    = (const float*)d_in[0];
    const float* wgt  = (const float*)d_in[1];
    const float* bias = (const float*)d_in[2];
    const void*  mask = d_in[3];
    float* out = (float*)d_out;

    build_lists_kernel<<<NBR, 256>>>(mask);
    x_transform_kernel<<<dim3(NBC / 4, MROWS / 32), 256>>>(x);
    w_transform_kernel<<<dim3(NBC / 4, NBR), 256>>>(wgt);
    dim3 grid(NBR, MROWS / MTILE);  // blockIdx.x = block row (fast), blockIdx.y = M tile
    bs_main_kernel<<<grid, 128>>>(bias, out);
}

// round 16
// speedup vs baseline: 2.1687x; 1.0231x over previous
#include <cuda_runtime.h>
#include <stdint.h>

// Block-sparse linear, GB300 (harness PTX = compute_103 -> no tcgen05/TMA).
// R16: R15 main kernel (M=64/warp fragment-major tf32, 175.8us) unchanged;
// w_transform now skips masked blocks (90% of wT writes, 66% of tile reads).
#define KDIM 4096
#define NDIM 4096
#define MROWS 8192
#define NBR 256       // OUT/16 block rows
#define NBC 256       // IN/16 block cols
#define MAXB 96       // cap on nonzero blocks per row (mean 25.6)
#define MTILE 256

// ---------------- device globals (no dynamic allocation allowed) ----------------
__device__ int g_es;
__device__ int g_cnt[NBR];
__device__ unsigned short g_cols[NBR * MAXB];
// xT: [c(256)][g32(256)][w=mf*2+ks(4)][lane(32)] x uint4  (134MB)
__device__ uint4 g_xT[(size_t)NBC * 256 * 4 * 32];
// wT: [r(256)][c(256)][ks(2)][lane(32)] x uint4  (67MB; masked blocks left stale, never read)
__device__ uint4 g_wT[(size_t)NBR * NBC * 2 * 32];

// ---------------- helpers ----------------
__device__ __forceinline__ uint32_t cvt_tf32(float f) {
    uint32_t r;
    asm("cvt.rna.tf32.f32 %0, %1;" : "=r"(r) : "f"(f));
    return r;
}
__device__ __forceinline__ void mma_tf32(float* c, const uint4& a, uint32_t b0, uint32_t b1) {
    asm volatile(
        "mma.sync.aligned.m16n8k8.row.col.f32.tf32.tf32.f32 "
        "{%0,%1,%2,%3}, {%4,%5,%6,%7}, {%8,%9}, {%0,%1,%2,%3};"
        : "+f"(c[0]), "+f"(c[1]), "+f"(c[2]), "+f"(c[3])
        : "r"(a.x), "r"(a.y), "r"(a.z), "r"(a.w), "r"(b0), "r"(b1));
}
__device__ __forceinline__ int detect_es(const void* mask) {
    const unsigned* w = (const unsigned*)mask;
    int es = 1;
    for (int i = 0; i < 4096; i++) {
        unsigned v = w[i];
        if (v == 0u) continue;
        if (v == 0x3F800000u) { es = 4; break; }
        if (v == 1u)          { es = 4; break; }
        if (v == 0x01010101u) { es = 1; break; }
        if (v == 0x3F803F80u || v == 0x3C003C00u) { es = 2; break; }
        es = 4; break;
    }
    return es;
}
__device__ __forceinline__ bool probe_mask(const void* mask, int es, int r, int c) {
    size_t idx = (size_t)(r * 16) * KDIM + (size_t)c * 16;   // block corner, element units
    if (es == 4)      return ((const unsigned*)mask)[idx] != 0u;
    else if (es == 2) return ((const unsigned short*)mask)[idx] != 0;
    else              return ((const unsigned char*)mask)[idx] != 0;
}

// ---------------- kernel 1: parallel per-row nonzero block lists ----------------
__global__ void __launch_bounds__(256)
build_lists_kernel(const void* __restrict__ mask) {
    __shared__ int s_es;
    __shared__ int s_wcnt[8];
    const int r = blockIdx.x;
    const int tid = threadIdx.x;
    if (tid == 0) {
        s_es = detect_es(mask);
        g_es = s_es;                       // publish for w_transform (stream-ordered)
    }
    __syncthreads();
    const int es = s_es;
    const bool nz = probe_mask(mask, es, r, tid);
    const unsigned ball = __ballot_sync(0xFFFFFFFFu, nz);
    const int wid = tid >> 5, lane = tid & 31;
    if (lane == 0) s_wcnt[wid] = __popc(ball);
    __syncthreads();
    int base = 0;
    #pragma unroll
    for (int i = 0; i < 8; i++) base += (i < wid) ? s_wcnt[i] : 0;
    const int pos = base + __popc(ball & ((1u << lane) - 1u));
    if (nz && pos < MAXB) g_cols[r * MAXB + pos] = (unsigned short)tid;
    if (tid == 255) {
        int tot = base + s_wcnt[7];
        g_cnt[r] = tot < MAXB ? tot : MAXB;
    }
}

// ---------------- kernel 2: x -> fragment-major tf32 (smem-staged, coalesced) ----------------
__global__ void __launch_bounds__(256)
x_transform_kernel(const float* __restrict__ x) {
    __shared__ float s[32][68];
    const int cbase = blockIdx.x * 4;
    const int g32   = blockIdx.y;
    const int tid = threadIdx.x;
    {
        const int row = tid >> 4;
        const int cc  = (tid & 15) * 4;
        const float* src = x + (size_t)(g32 * 32) * KDIM + cbase * 16;
        #pragma unroll
        for (int h = 0; h < 2; h++) {
            float4 v = *(const float4*)(src + (size_t)(row + h * 16) * KDIM + cc);
            s[row + h * 16][cc]     = v.x;
            s[row + h * 16][cc + 1] = v.y;
            s[row + h * 16][cc + 2] = v.z;
            s[row + h * 16][cc + 3] = v.w;
        }
    }
    __syncthreads();
    #pragma unroll
    for (int rep = 0; rep < 2; rep++) {
        const int o    = tid + rep * 256;
        const int cb   = o >> 7;
        const int w    = (o >> 5) & 3;
        const int lane = o & 31;
        const int mf = w >> 1, ks = w & 1;
        const int g = lane >> 2, t4 = lane & 3;
        const int r0 = mf * 16 + g;
        const int cc = cb * 16 + ks * 8 + t4;
        uint4 v;
        v.x = cvt_tf32(s[r0][cc]);
        v.y = cvt_tf32(s[r0 + 8][cc]);
        v.z = cvt_tf32(s[r0][cc + 4]);
        v.w = cvt_tf32(s[r0 + 8][cc + 4]);
        g_xT[((size_t)((cbase + cb) * 256 + g32) * 4 + w) * 32 + lane] = v;
    }
}

// ---------------- kernel 3: w -> fragment-major tf32, masked blocks skipped ----------------
__global__ void __launch_bounds__(256)
w_transform_kernel(const float* __restrict__ w, const void* __restrict__ mask) {
    __shared__ float s[16][68];
    __shared__ int s_nz[4];
    const int cbase = blockIdx.x * 4;
    const int r     = blockIdx.y;
    const int tid = threadIdx.x;

    if (tid < 4) s_nz[tid] = probe_mask(mask, g_es, r, cbase + tid) ? 1 : 0;
    __syncthreads();
    if ((s_nz[0] | s_nz[1] | s_nz[2] | s_nz[3]) == 0) return;   // uniform: whole tile masked

    {
        const int row = tid >> 4;
        const int cc  = (tid & 15) * 4;
        float4 v = *(const float4*)(w + (size_t)(r * 16 + row) * KDIM + cbase * 16 + cc);
        s[row][cc] = v.x; s[row][cc + 1] = v.y; s[row][cc + 2] = v.z; s[row][cc + 3] = v.w;
    }
    __syncthreads();
    {
        const int cb   = tid >> 6;
        if (s_nz[cb]) {                    // emit only live blocks (~10%)
            const int ks   = (tid >> 5) & 1;
            const int lane = tid & 31;
            const int g = lane >> 2, t4 = lane & 3;
            const int cc = cb * 16 + ks * 8 + t4;
            uint4 v;
            v.x = cvt_tf32(s[g][cc]);
            v.y = cvt_tf32(s[g][cc + 4]);
            v.z = cvt_tf32(s[g + 8][cc]);
            v.w = cvt_tf32(s[g + 8][cc + 4]);
            g_wT[((size_t)(r * 256 + (cbase + cb)) * 2 + ks) * 32 + lane] = v;
        }
    }
}

// ---------------- kernel 4: main — M=64 per warp, ping-pong, barrier-free (R15) ----------------
__global__ void __launch_bounds__(128, 3)
bs_main_kernel(const float* __restrict__ bias, float* __restrict__ out) {
    __shared__ unsigned short s_cols[MAXB];

    const int r     = blockIdx.x;
    const int mBase = blockIdx.y * MTILE;
    const int tid = threadIdx.x;
    const int wid = tid >> 5;
    const int lid = tid & 31;
    const int g = lid >> 2, t4 = lid & 3;

    const int cnt = g_cnt[r];
    if (tid < cnt) s_cols[tid] = g_cols[r * MAXB + tid];
    __syncthreads();

    const int ocol = r * 16;

    if (cnt == 0) {
        float4 b0 = *(const float4*)(bias + ocol);
        float4 b1 = *(const float4*)(bias + ocol + 4);
        float4 b2 = *(const float4*)(bias + ocol + 8);
        float4 b3 = *(const float4*)(bias + ocol + 12);
        #pragma unroll
        for (int h = 0; h < 2; h++) {
            float4* dst = (float4*)(out + (size_t)(mBase + h * 128 + tid) * NDIM + ocol);
            dst[0] = b0; dst[1] = b1; dst[2] = b2; dst[3] = b3;
        }
        return;
    }

    const size_t g32a = (size_t)blockIdx.y * 8 + wid * 2;

    float acc[8][4];
    #pragma unroll
    for (int i = 0; i < 8; i++)
        #pragma unroll
        for (int j = 0; j < 4; j++) acc[i][j] = 0.0f;

    auto ldfrag = [&](int q, uint4* A, uint4* B) {
        const int c = s_cols[q];
        const uint4* xp = &g_xT[((size_t)c * 256 + g32a) * 128 + lid];
        #pragma unroll
        for (int j = 0; j < 8; j++) A[j] = xp[j * 32];
        const uint4* wp = &g_wT[((size_t)r * 256 + c) * 64 + lid];
        B[0] = wp[0];
        B[1] = wp[32];
    };

    auto compute = [&](const uint4* A, const uint4* B) {
        #pragma unroll
        for (int ks = 0; ks < 2; ks++) {
            const uint32_t b00 = B[ks].x;
            const uint32_t b01 = B[ks].y;
            const uint32_t b10 = B[ks].z;
            const uint32_t b11 = B[ks].w;
            #pragma unroll
            for (int mf = 0; mf < 4; mf++) {
                const uint4& a = A[mf * 2 + ks];
                mma_tf32(acc[mf * 2 + 0], a, b00, b01);
                mma_tf32(acc[mf * 2 + 1], a, b10, b11);
            }
        }
    };

    uint4 A0[8], B0[2], A1[8], B1[2];
    ldfrag(0, A0, B0);
    int q = 0;
    for (;;) {
        const int q1 = (q + 1 < cnt) ? q + 1 : q;
        ldfrag(q1, A1, B1);
        compute(A0, B0);
        if (++q >= cnt) break;
        const int q2 = (q + 1 < cnt) ? q + 1 : q;
        ldfrag(q2, A0, B0);
        compute(A1, B1);
        if (++q >= cnt) break;
    }

    #pragma unroll
    for (int nf = 0; nf < 2; nf++) {
        const int col = ocol + nf * 8 + t4 * 2;
        const float b0 = bias[col];
        const float b1 = bias[col + 1];
        #pragma unroll
        for (int mf = 0; mf < 4; mf++) {
            const float* c = acc[mf * 2 + nf];
            const int row0 = mBase + wid * 64 + mf * 16 + g;
            float2 v0 = make_float2(c[0] + b0, c[1] + b1);
            float2 v1 = make_float2(c[2] + b0, c[3] + b1);
            *(float2*)(out + (size_t)row0 * NDIM + col) = v0;
            *(float2*)(out + (size_t)(row0 + 8) * NDIM + col) = v1;
        }
    }
}

// ---------------- launch ----------------
extern "C" void kernel_launch(void* const* d_in, const int* in_sizes, int n_in,
                              void* d_out, int out_size) {
    const float* x    = (const float*)d_in[0];
    const float* wgt  = (const float*)d_in[1];
    const float* bias = (const float*)d_in[2];
    const void*  mask = d_in[3];
    float* out = (float*)d_out;

    build_lists_kernel<<<NBR, 256>>>(mask);
    x_transform_kernel<<<dim3(NBC / 4, MROWS / 32), 256>>>(x);
    w_transform_kernel<<<dim3(NBC / 4, NBR), 256>>>(wgt, mask);
    dim3 grid(NBR, MROWS / MTILE);
    bs_main_kernel<<<grid, 128>>>(bias, out);
}